// round 1
// baseline (speedup 1.0000x reference)
#include <cuda_runtime.h>
#include <math.h>

// ---------------------------------------------------------------------------
// MultiLevelGCN: x = relu((A@x) @ W_i^T + b_i) x3 ; gather; 2-layer MLP+softmax
// Dominant cost: 3x SGEMM [16384x16384] @ [16384x256]  (~412 GFLOP fp32)
// Strategy: tiled SGEMM (BM=BN=128, BK=16, 8x8 micro-tile) using Blackwell
// packed fma.rn.f32x2 (2 fp32 FMA lanes per issue slot -> 2x fp32 throughput
// vs 3-reg FFMA per B300 SASS measurements), with register prefetch of the
// next global tile overlapping compute.
// ---------------------------------------------------------------------------

#define N_NODES 16384
#define F_DIM   256
#define NIDX    8192
#define MLPH    128
#define NCLS    16

// Scratch ping-pong buffers (allocation-free rule: __device__ globals)
__device__ float g_y[N_NODES * F_DIM];   // A @ x result
__device__ float g_x[N_NODES * F_DIM];   // layer activations

// ---- packed f32x2 helpers --------------------------------------------------
__device__ __forceinline__ void fma2(unsigned long long& d,
                                     unsigned long long a,
                                     unsigned long long b) {
    asm("fma.rn.f32x2 %0, %1, %2, %0;" : "+l"(d) : "l"(a), "l"(b));
}
__device__ __forceinline__ unsigned long long bcast2(float x) {
    unsigned long long r;
    asm("mov.b64 %0, {%1, %1};" : "=l"(r) : "f"(x));
    return r;
}
__device__ __forceinline__ void unpack2(unsigned long long v, float& lo, float& hi) {
    asm("mov.b64 {%0, %1}, %2;" : "=f"(lo), "=f"(hi) : "l"(v));
}

// ---------------------------------------------------------------------------
// Generic SGEMM: C[M,N] = op( A' @ B' ) (+bias, relu)
//   A' rows: A[row,:] (row-major, stride K), optionally gathered via gidx
//   BT=false: B is [K,N] row-major (B'[k,n] = B[k*N+n])
//   BT=true : B is [N,K] row-major (B'[k,n] = B[n*K+k])  i.e. X @ B^T
// All dims assumed multiples of the tile sizes (true for this problem).
// ---------------------------------------------------------------------------
template<bool BT, bool RELU, bool GATHER>
__global__ __launch_bounds__(256, 2)
void sgemm_kernel(const float* __restrict__ A, const float* __restrict__ B,
                  const float* __restrict__ bias, const int* __restrict__ gidx,
                  float* __restrict__ C, int M, int N, int K)
{
    constexpr int BM = 128, BN = 128, BK = 16;
    __shared__ float As[BK][BM];
    __shared__ float Bs[BK][BN];

    const int tid = threadIdx.x;          // 0..255
    const int tx  = tid & 15;             // micro-tile col group
    const int ty  = tid >> 4;             // micro-tile row group
    const int rowBase = blockIdx.y * BM;
    const int colBase = blockIdx.x * BN;

    // --- global->reg load mapping: two float4 slots per thread per tile ----
    // A tile: 128 rows x 16 cols -> 512 float4; slot f = tid, tid+256
    const int ar0 = tid >> 2;               // 0..63
    const int ar1 = (tid + 256) >> 2;       // 64..127
    const int ac  = (tid & 3) * 4;          // k offset within tile
    long aRow0 = GATHER ? (long)gidx[rowBase + ar0] : (long)(rowBase + ar0);
    long aRow1 = GATHER ? (long)gidx[rowBase + ar1] : (long)(rowBase + ar1);
    const float* Ap0 = A + aRow0 * (long)K + ac;
    const float* Ap1 = A + aRow1 * (long)K + ac;

    const float* Bp0;
    const float* Bp1;
    int bk0, bc0, bk1, bc1;
    if (BT) {
        // B tile: 128 n-rows x 16 k-cols (transposed into Bs)
        bk0 = (tid & 3) * 4;  bc0 = tid >> 2;          // n-local 0..63
        bk1 = bk0;            bc1 = (tid + 256) >> 2;  // n-local 64..127
        Bp0 = B + (long)(colBase + bc0) * K + bk0;
        Bp1 = B + (long)(colBase + bc1) * K + bk1;
    } else {
        // B tile: 16 k-rows x 128 n-cols, direct float4
        bk0 = tid >> 5;           bc0 = (tid & 31) * 4;
        bk1 = (tid + 256) >> 5;   bc1 = bc0;
        Bp0 = B + (long)bk0 * N + colBase + bc0;
        Bp1 = B + (long)bk1 * N + colBase + bc1;
    }

    unsigned long long acc[8][4];
    #pragma unroll
    for (int i = 0; i < 8; ++i)
        #pragma unroll
        for (int j = 0; j < 4; ++j) acc[i][j] = 0ull;  // packed (0.f, 0.f)

    const int nt = K / BK;

    // prologue: prefetch tile 0
    float4 av0 = *(const float4*)Ap0;
    float4 av1 = *(const float4*)Ap1;
    float4 bv0 = *(const float4*)Bp0;
    float4 bv1 = *(const float4*)Bp1;

    for (int t = 0; t < nt; ++t) {
        // stage regs -> smem (A transposed; B transposed iff BT)
        As[ac + 0][ar0] = av0.x;  As[ac + 1][ar0] = av0.y;
        As[ac + 2][ar0] = av0.z;  As[ac + 3][ar0] = av0.w;
        As[ac + 0][ar1] = av1.x;  As[ac + 1][ar1] = av1.y;
        As[ac + 2][ar1] = av1.z;  As[ac + 3][ar1] = av1.w;
        if (BT) {
            Bs[bk0 + 0][bc0] = bv0.x;  Bs[bk0 + 1][bc0] = bv0.y;
            Bs[bk0 + 2][bc0] = bv0.z;  Bs[bk0 + 3][bc0] = bv0.w;
            Bs[bk1 + 0][bc1] = bv1.x;  Bs[bk1 + 1][bc1] = bv1.y;
            Bs[bk1 + 2][bc1] = bv1.z;  Bs[bk1 + 3][bc1] = bv1.w;
        } else {
            *(float4*)&Bs[bk0][bc0] = bv0;
            *(float4*)&Bs[bk1][bc1] = bv1;
        }
        __syncthreads();

        // prefetch next tile (overlaps with compute below)
        if (t + 1 < nt) {
            Ap0 += BK;  Ap1 += BK;
            av0 = *(const float4*)Ap0;
            av1 = *(const float4*)Ap1;
            if (BT) { Bp0 += BK; Bp1 += BK; }
            else    { Bp0 += (long)BK * N; Bp1 += (long)BK * N; }
            bv0 = *(const float4*)Bp0;
            bv1 = *(const float4*)Bp1;
        }

        // compute 8x8 micro-tile as 8x4 packed f32x2 FMAs per k
        #pragma unroll
        for (int k = 0; k < BK; ++k) {
            float a[8];
            *(float4*)&a[0] = *(const float4*)&As[k][ty * 8 + 0];
            *(float4*)&a[4] = *(const float4*)&As[k][ty * 8 + 4];
            unsigned long long b[4];
            b[0] = *(const unsigned long long*)&Bs[k][tx * 8 + 0];
            b[1] = *(const unsigned long long*)&Bs[k][tx * 8 + 2];
            b[2] = *(const unsigned long long*)&Bs[k][tx * 8 + 4];
            b[3] = *(const unsigned long long*)&Bs[k][tx * 8 + 6];
            #pragma unroll
            for (int i = 0; i < 8; ++i) {
                unsigned long long aa = bcast2(a[i]);
                fma2(acc[i][0], aa, b[0]);
                fma2(acc[i][1], aa, b[1]);
                fma2(acc[i][2], aa, b[2]);
                fma2(acc[i][3], aa, b[3]);
            }
        }
        __syncthreads();
    }

    // --- epilogue ----------------------------------------------------------
    const int crow = rowBase + ty * 8;
    const int ccol = colBase + tx * 8;
    float bb[8];
    if (RELU) {
        #pragma unroll
        for (int j = 0; j < 8; ++j) bb[j] = bias[ccol + j];
    }
    #pragma unroll
    for (int i = 0; i < 8; ++i) {
        float v[8];
        #pragma unroll
        for (int j = 0; j < 4; ++j) unpack2(acc[i][j], v[2 * j], v[2 * j + 1]);
        if (RELU) {
            #pragma unroll
            for (int j = 0; j < 8; ++j) v[j] = fmaxf(v[j] + bb[j], 0.0f);
        }
        float* cp = C + (long)(crow + i) * N + ccol;
        *(float4*)&cp[0] = *(float4*)&v[0];
        *(float4*)&cp[4] = *(float4*)&v[4];
    }
}

// ---------------------------------------------------------------------------
// MLP layer 2 + softmax: out[r, c] = softmax_c( enc[r,:] . w2[c,:] + b2[c] )
// block = (16 classes, 16 rows); w2 (16x128) staged in smem.
// ---------------------------------------------------------------------------
__global__ __launch_bounds__(256)
void mlp2_softmax_kernel(const float* __restrict__ enc,
                         const float* __restrict__ w2,
                         const float* __restrict__ b2,
                         float* __restrict__ out)
{
    __shared__ float w2s[NCLS * MLPH];
    __shared__ float b2s[NCLS];
    const int tid = threadIdx.y * 16 + threadIdx.x;
    for (int i = tid; i < NCLS * MLPH; i += 256) w2s[i] = w2[i];
    if (tid < NCLS) b2s[tid] = b2[tid];
    __syncthreads();

    const int row = blockIdx.x * 16 + threadIdx.y;
    const int c   = threadIdx.x;

    const float4* e4 = (const float4*)(enc + (long)row * MLPH);
    const float4* w4 = (const float4*)(w2s + c * MLPH);
    float acc = 0.0f;
    #pragma unroll
    for (int k = 0; k < MLPH / 4; ++k) {
        float4 e = e4[k];
        float4 w = w4[k];
        acc += e.x * w.x + e.y * w.y + e.z * w.z + e.w * w.w;
    }
    acc += b2s[c];

    // softmax across the 16 class lanes (aligned 16-lane groups within warps)
    float m = acc;
    #pragma unroll
    for (int d = 8; d >= 1; d >>= 1)
        m = fmaxf(m, __shfl_xor_sync(0xffffffffu, m, d, 16));
    float e = expf(acc - m);
    float s = e;
    #pragma unroll
    for (int d = 8; d >= 1; d >>= 1)
        s += __shfl_xor_sync(0xffffffffu, s, d, 16);
    out[(long)row * NCLS + c] = e / s;
}

// ---------------------------------------------------------------------------
extern "C" void kernel_launch(void* const* d_in, const int* in_sizes, int n_in,
                              void* d_out, int out_size)
{
    const float* A   = (const float*)d_in[0];   // [16384,16384]
    const float* x0  = (const float*)d_in[1];   // [16384,256]
    const float* gw  = (const float*)d_in[2];   // [3,256,256]
    const float* gb  = (const float*)d_in[3];   // [3,256]
    const float* w1  = (const float*)d_in[4];   // [128,256]
    const float* b1  = (const float*)d_in[5];   // [128]
    const float* w2  = (const float*)d_in[6];   // [16,128]
    const float* b2  = (const float*)d_in[7];   // [16]
    const int*   idx = (const int*)d_in[8];     // [8192]
    float* out = (float*)d_out;                 // encode [8192,128] ++ out [8192,16]

    // Resolve device-global scratch addresses once (outside graph capture: the
    // first correctness call performs this; captured replays see cached values).
    static float* gy = nullptr;
    static float* gx = nullptr;
    if (!gy) {
        cudaGetSymbolAddress((void**)&gy, g_y);
        cudaGetSymbolAddress((void**)&gx, g_x);
    }

    const dim3 blk(256);
    const dim3 gridBig(F_DIM / 128, N_NODES / 128);   // (2,128)
    const dim3 gridEnc(MLPH / 128, NIDX / 128);       // (1,64)

    const float* xin = x0;
    for (int l = 0; l < 3; ++l) {
        // g_y = A @ x     [16384,256], K = 16384
        sgemm_kernel<false, false, false><<<gridBig, blk>>>(
            A, xin, nullptr, nullptr, gy, N_NODES, F_DIM, N_NODES);
        // g_x = relu(g_y @ W_l^T + b_l)   K = 256
        sgemm_kernel<true, true, false><<<gridBig, blk>>>(
            gy, gw + (long)l * F_DIM * F_DIM, gb + (long)l * F_DIM, nullptr,
            gx, N_NODES, F_DIM, F_DIM);
        xin = gx;
    }

    // encode = relu(g_x[idx] @ w1^T + b1)  -> d_out[0 : 8192*128]
    sgemm_kernel<true, true, true><<<gridEnc, blk>>>(
        gx, w1, b1, idx, out, NIDX, MLPH, F_DIM);

    // out = softmax(encode @ w2^T + b2)    -> d_out[8192*128 : ]
    mlp2_softmax_kernel<<<NIDX / 16, dim3(16, 16)>>>(
        out, w2, b2, out + (long)NIDX * MLPH);
}

// round 3
// speedup vs baseline: 2.2563x; 2.2563x over previous
#include <cuda_runtime.h>
#include <cuda_bf16.h>
#include <math.h>
#include <stdint.h>

// ---------------------------------------------------------------------------
// MultiLevelGCN on B200 (sm_100a)
//   x = relu((A@x) @ W_i^T + b_i) x3 ; gather; MLP+softmax
// A@x (3x [16384x16384]@[16384x256], 412 GFLOP) on tensor cores via bf16
// hi/lo split (3 HMMA passes, fp32 accum; Al*Xl term dropped ~2^-18).
// Small GEMMs (X@W^T, encoder) on the fp32 f32x2 path.
// ---------------------------------------------------------------------------

#define N_NODES 16384
#define F_DIM   256
#define NIDX    8192
#define MLPH    128
#define NCLS    16

// ---- scratch (allocation-free rule: __device__ globals) -------------------
__device__ __align__(16) float g_y[N_NODES * F_DIM];            // A @ x
__device__ __align__(16) float g_x[N_NODES * F_DIM];            // activations
__device__ __align__(16) __nv_bfloat16 g_Ah[(long)N_NODES * N_NODES]; // 512MB
__device__ __align__(16) __nv_bfloat16 g_Al[(long)N_NODES * N_NODES]; // 512MB
__device__ __align__(16) __nv_bfloat16 g_Xh[F_DIM * N_NODES];   // X^T hi
__device__ __align__(16) __nv_bfloat16 g_Xl[F_DIM * N_NODES];   // X^T lo

// ---------------------------------------------------------------------------
// PTX helpers
// ---------------------------------------------------------------------------
__device__ __forceinline__ uint32_t smem_u32(const void* p) {
    uint32_t a;
    asm("{ .reg .u64 t; cvta.to.shared.u64 t, %1; cvt.u32.u64 %0, t; }"
        : "=r"(a) : "l"(p));
    return a;
}
__device__ __forceinline__ void cp16(uint32_t s, const void* g) {
    asm volatile("cp.async.cg.shared.global [%0], [%1], 16;" :: "r"(s), "l"(g));
}
__device__ __forceinline__ void cp_commit() {
    asm volatile("cp.async.commit_group;");
}
template<int N_> __device__ __forceinline__ void cp_wait() {
    asm volatile("cp.async.wait_group %0;" :: "n"(N_));
}
__device__ __forceinline__ void ldm_x4(uint32_t* r, uint32_t addr) {
    asm volatile("ldmatrix.sync.aligned.m8n8.x4.shared.b16 {%0,%1,%2,%3}, [%4];"
        : "=r"(r[0]), "=r"(r[1]), "=r"(r[2]), "=r"(r[3]) : "r"(addr));
}
__device__ __forceinline__ void ldm_x2(uint32_t* r, uint32_t addr) {
    asm volatile("ldmatrix.sync.aligned.m8n8.x2.shared.b16 {%0,%1}, [%2];"
        : "=r"(r[0]), "=r"(r[1]) : "r"(addr));
}
__device__ __forceinline__ void mma_bf16(float* c, const uint32_t* a, const uint32_t* b) {
    asm volatile(
        "mma.sync.aligned.m16n8k16.row.col.f32.bf16.bf16.f32 "
        "{%0,%1,%2,%3}, {%4,%5,%6,%7}, {%8,%9}, {%0,%1,%2,%3};"
        : "+f"(c[0]), "+f"(c[1]), "+f"(c[2]), "+f"(c[3])
        : "r"(a[0]), "r"(a[1]), "r"(a[2]), "r"(a[3]), "r"(b[0]), "r"(b[1]));
}
__device__ __forceinline__ void fma2(unsigned long long& d, unsigned long long a,
                                     unsigned long long b) {
    asm("fma.rn.f32x2 %0, %1, %2, %0;" : "+l"(d) : "l"(a), "l"(b));
}
__device__ __forceinline__ unsigned long long bcast2(float x) {
    unsigned long long r;
    asm("mov.b64 %0, {%1, %1};" : "=l"(r) : "f"(x));
    return r;
}
__device__ __forceinline__ void unpack2(unsigned long long v, float& lo, float& hi) {
    asm("mov.b64 {%0, %1}, %2;" : "=f"(lo), "=f"(hi) : "l"(v));
}

// ---------------------------------------------------------------------------
// A split: fp32 -> bf16 hi + bf16 lo (elementwise, 8 elems/thread)
// ---------------------------------------------------------------------------
__global__ __launch_bounds__(256)
void split_a_kernel(const float* __restrict__ src,
                    __nv_bfloat16* __restrict__ hi,
                    __nv_bfloat16* __restrict__ lo)
{
    long i = ((long)blockIdx.x * blockDim.x + threadIdx.x) * 8;
    float4 v0 = *(const float4*)(src + i);
    float4 v1 = *(const float4*)(src + i + 4);
    float f[8] = {v0.x, v0.y, v0.z, v0.w, v1.x, v1.y, v1.z, v1.w};
    __nv_bfloat16 h[8], l[8];
    #pragma unroll
    for (int j = 0; j < 8; ++j) {
        h[j] = __float2bfloat16(f[j]);
        l[j] = __float2bfloat16(f[j] - __bfloat162float(h[j]));
    }
    *(uint4*)(hi + i) = *(uint4*)h;
    *(uint4*)(lo + i) = *(uint4*)l;
}

// ---------------------------------------------------------------------------
// X split + transpose: fp32 [16384,256] -> bf16 X^T hi/lo [256,16384]
// block (32,8), grid (256/32, 16384/32)
// ---------------------------------------------------------------------------
__global__ __launch_bounds__(256)
void split_xt_kernel(const float* __restrict__ x,
                     __nv_bfloat16* __restrict__ hi,
                     __nv_bfloat16* __restrict__ lo)
{
    __shared__ float tile[32][33];
    const int tx = threadIdx.x, ty = threadIdx.y;
    const int rb = blockIdx.y * 32;      // k rows (node dim)
    const int cb = blockIdx.x * 32;      // n cols (feature dim)
    #pragma unroll
    for (int i = 0; i < 4; ++i)
        tile[ty + 8 * i][tx] = x[(long)(rb + ty + 8 * i) * F_DIM + cb + tx];
    __syncthreads();
    #pragma unroll
    for (int i = 0; i < 4; ++i) {
        float v = tile[tx][ty + 8 * i];
        __nv_bfloat16 h = __float2bfloat16(v);
        __nv_bfloat16 l = __float2bfloat16(v - __bfloat162float(h));
        long o = (long)(cb + ty + 8 * i) * N_NODES + rb + tx;
        hi[o] = h;
        lo[o] = l;
    }
}

// ---------------------------------------------------------------------------
// Big GEMM: Y[16384,256] = A @ X  via bf16 split, HMMA m16n8k16
// BM=128 BN=128 BK=32, 256 threads, warp grid 2x4 (warp tile 64x32)
// smem: 2 stages x 4 tiles (Ah,Al,Xh,Xl) x 128 rows x 40 halfs (pad) = 80KB
// ---------------------------------------------------------------------------
#define GK      N_NODES
#define ROWPAD  40                         // halfs per smem row
#define TILE_B  (128 * ROWPAD * 2)         // 10240 bytes per tile
#define STAGE_B (4 * TILE_B)               // 40960 bytes per stage

__global__ __launch_bounds__(256, 2)
void gcn_ax_bf16_kernel(const __nv_bfloat16* __restrict__ Ah,
                        const __nv_bfloat16* __restrict__ Al,
                        const __nv_bfloat16* __restrict__ Xh,
                        const __nv_bfloat16* __restrict__ Xl,
                        float* __restrict__ Y)
{
    extern __shared__ __nv_bfloat16 smem[];
    const uint32_t sbase = smem_u32(smem);

    const int tid  = threadIdx.x;
    const int lane = tid & 31;
    const int wid  = tid >> 5;
    const int wr   = wid & 1;              // warp row (0..1) -> m offset 64*wr
    const int wc   = wid >> 1;             // warp col (0..3) -> n offset 32*wc
    const int mBase = blockIdx.y * 128;
    const int nBase = blockIdx.x * 128;

    // ---- copy mapping: chunk c = tid handles rows r0 and r0+64 -----------
    const int r0 = tid >> 2;               // 0..63
    const int q0 = tid & 3;                // 16B chunk within 64B row
    const uint32_t d0 = (uint32_t)(r0 * ROWPAD + q0 * 8) * 2;  // smem byte off
    const uint32_t d1 = d0 + 64 * ROWPAD * 2;
    const long gstep = (long)64 * GK;      // +64 rows in gmem (halfs)

    const __nv_bfloat16* pAh = Ah + (long)(mBase + r0) * GK + q0 * 8;
    const __nv_bfloat16* pAl = Al + (long)(mBase + r0) * GK + q0 * 8;
    const __nv_bfloat16* pXh = Xh + (long)(nBase + r0) * GK + q0 * 8;
    const __nv_bfloat16* pXl = Xl + (long)(nBase + r0) * GK + q0 * 8;

    // ---- ldmatrix per-lane offsets ----------------------------------------
    const int la = lane & 15, ha = lane >> 4;        // A frag (x4)
    const int lb = lane & 7,  hb = (lane >> 3) & 1;  // B frag (x2)

    float acc[4][4][4];
    #pragma unroll
    for (int i = 0; i < 4; ++i)
        #pragma unroll
        for (int j = 0; j < 4; ++j)
            #pragma unroll
            for (int k = 0; k < 4; ++k) acc[i][j][k] = 0.0f;

    const int nk = GK / 32;                // 512 k-tiles

    // ---- stage copy --------------------------------------------------------
    auto copy_stage = [&](int stage, long kt) {
        uint32_t b = sbase + stage * STAGE_B;
        cp16(b + 0 * TILE_B + d0, pAh + kt);
        cp16(b + 0 * TILE_B + d1, pAh + kt + gstep);
        cp16(b + 1 * TILE_B + d0, pAl + kt);
        cp16(b + 1 * TILE_B + d1, pAl + kt + gstep);
        cp16(b + 2 * TILE_B + d0, pXh + kt);
        cp16(b + 2 * TILE_B + d1, pXh + kt + gstep);
        cp16(b + 3 * TILE_B + d0, pXl + kt);
        cp16(b + 3 * TILE_B + d1, pXl + kt + gstep);
        cp_commit();
    };

    copy_stage(0, 0);

    for (int t = 0; t < nk; ++t) {
        if (t + 1 < nk) {
            copy_stage((t + 1) & 1, (long)(t + 1) * 32);
            cp_wait<1>();
        } else {
            cp_wait<0>();
        }
        __syncthreads();

        const uint32_t sAh = sbase + (t & 1) * STAGE_B;
        const uint32_t sAl = sAh + TILE_B;
        const uint32_t sXh = sAh + 2 * TILE_B;
        const uint32_t sXl = sAh + 3 * TILE_B;

        #pragma unroll
        for (int kk = 0; kk < 2; ++kk) {
            const int ko = kk * 16;
            uint32_t bh[4][2], bl[4][2];
            #pragma unroll
            for (int ni = 0; ni < 4; ++ni) {
                uint32_t off = (uint32_t)((wc * 32 + ni * 8 + lb) * ROWPAD
                                          + ko + hb * 8) * 2;
                ldm_x2(bh[ni], sXh + off);
                ldm_x2(bl[ni], sXl + off);
            }
            uint32_t a[4][4];
            #pragma unroll
            for (int mi = 0; mi < 4; ++mi) {
                uint32_t off = (uint32_t)((wr * 64 + mi * 16 + la) * ROWPAD
                                          + ko + ha * 8) * 2;
                ldm_x4(a[mi], sAh + off);
            }
            #pragma unroll
            for (int mi = 0; mi < 4; ++mi)
                #pragma unroll
                for (int ni = 0; ni < 4; ++ni) {
                    mma_bf16(acc[mi][ni], a[mi], bh[ni]);
                    mma_bf16(acc[mi][ni], a[mi], bl[ni]);
                }
            #pragma unroll
            for (int mi = 0; mi < 4; ++mi) {
                uint32_t off = (uint32_t)((wr * 64 + mi * 16 + la) * ROWPAD
                                          + ko + ha * 8) * 2;
                ldm_x4(a[mi], sAl + off);
            }
            #pragma unroll
            for (int mi = 0; mi < 4; ++mi)
                #pragma unroll
                for (int ni = 0; ni < 4; ++ni)
                    mma_bf16(acc[mi][ni], a[mi], bh[ni]);
        }
        __syncthreads();
    }

    // ---- epilogue ----------------------------------------------------------
    const int g  = lane >> 2;
    const int tg = lane & 3;
    #pragma unroll
    for (int mi = 0; mi < 4; ++mi) {
        const int row = mBase + wr * 64 + mi * 16 + g;
        #pragma unroll
        for (int ni = 0; ni < 4; ++ni) {
            const int col = nBase + wc * 32 + ni * 8 + tg * 2;
            float2 v0 = make_float2(acc[mi][ni][0], acc[mi][ni][1]);
            float2 v1 = make_float2(acc[mi][ni][2], acc[mi][ni][3]);
            *(float2*)(Y + (long)row * F_DIM + col)       = v0;
            *(float2*)(Y + (long)(row + 8) * F_DIM + col) = v1;
        }
    }
}

// ---------------------------------------------------------------------------
// fp32 f32x2 SGEMM (small K=256 GEMMs): C = relu(A' @ B'^T + b)
// ---------------------------------------------------------------------------
template<bool RELU, bool GATHER>
__global__ __launch_bounds__(256, 2)
void sgemm_bt_kernel(const float* __restrict__ A, const float* __restrict__ B,
                     const float* __restrict__ bias, const int* __restrict__ gidx,
                     float* __restrict__ C, int M, int N, int K)
{
    constexpr int BM = 128, BN = 128, BK = 16;
    __shared__ float As[BK][BM];
    __shared__ float Bs[BK][BN];

    const int tid = threadIdx.x;
    const int tx  = tid & 15;
    const int ty  = tid >> 4;
    const int rowBase = blockIdx.y * BM;
    const int colBase = blockIdx.x * BN;

    const int ar0 = tid >> 2;
    const int ar1 = (tid + 256) >> 2;
    const int ac  = (tid & 3) * 4;
    long aRow0 = GATHER ? (long)gidx[rowBase + ar0] : (long)(rowBase + ar0);
    long aRow1 = GATHER ? (long)gidx[rowBase + ar1] : (long)(rowBase + ar1);
    const float* Ap0 = A + aRow0 * (long)K + ac;
    const float* Ap1 = A + aRow1 * (long)K + ac;

    const int bk0 = (tid & 3) * 4, bc0 = tid >> 2;
    const int bc1 = (tid + 256) >> 2;
    const float* Bp0 = B + (long)(colBase + bc0) * K + bk0;
    const float* Bp1 = B + (long)(colBase + bc1) * K + bk0;

    unsigned long long acc[8][4];
    #pragma unroll
    for (int i = 0; i < 8; ++i)
        #pragma unroll
        for (int j = 0; j < 4; ++j) acc[i][j] = 0ull;

    const int nt = K / BK;
    float4 av0 = *(const float4*)Ap0;
    float4 av1 = *(const float4*)Ap1;
    float4 bv0 = *(const float4*)Bp0;
    float4 bv1 = *(const float4*)Bp1;

    for (int t = 0; t < nt; ++t) {
        As[ac + 0][ar0] = av0.x;  As[ac + 1][ar0] = av0.y;
        As[ac + 2][ar0] = av0.z;  As[ac + 3][ar0] = av0.w;
        As[ac + 0][ar1] = av1.x;  As[ac + 1][ar1] = av1.y;
        As[ac + 2][ar1] = av1.z;  As[ac + 3][ar1] = av1.w;
        Bs[bk0 + 0][bc0] = bv0.x;  Bs[bk0 + 1][bc0] = bv0.y;
        Bs[bk0 + 2][bc0] = bv0.z;  Bs[bk0 + 3][bc0] = bv0.w;
        Bs[bk0 + 0][bc1] = bv1.x;  Bs[bk0 + 1][bc1] = bv1.y;
        Bs[bk0 + 2][bc1] = bv1.z;  Bs[bk0 + 3][bc1] = bv1.w;
        __syncthreads();

        if (t + 1 < nt) {
            Ap0 += BK;  Ap1 += BK;  Bp0 += BK;  Bp1 += BK;
            av0 = *(const float4*)Ap0;
            av1 = *(const float4*)Ap1;
            bv0 = *(const float4*)Bp0;
            bv1 = *(const float4*)Bp1;
        }

        #pragma unroll
        for (int k = 0; k < BK; ++k) {
            float a[8];
            *(float4*)&a[0] = *(const float4*)&As[k][ty * 8 + 0];
            *(float4*)&a[4] = *(const float4*)&As[k][ty * 8 + 4];
            unsigned long long b[4];
            b[0] = *(const unsigned long long*)&Bs[k][tx * 8 + 0];
            b[1] = *(const unsigned long long*)&Bs[k][tx * 8 + 2];
            b[2] = *(const unsigned long long*)&Bs[k][tx * 8 + 4];
            b[3] = *(const unsigned long long*)&Bs[k][tx * 8 + 6];
            #pragma unroll
            for (int i = 0; i < 8; ++i) {
                unsigned long long aa = bcast2(a[i]);
                fma2(acc[i][0], aa, b[0]);
                fma2(acc[i][1], aa, b[1]);
                fma2(acc[i][2], aa, b[2]);
                fma2(acc[i][3], aa, b[3]);
            }
        }
        __syncthreads();
    }

    const int crow = rowBase + ty * 8;
    const int ccol = colBase + tx * 8;
    float bb[8];
    #pragma unroll
    for (int j = 0; j < 8; ++j) bb[j] = bias[ccol + j];
    #pragma unroll
    for (int i = 0; i < 8; ++i) {
        float v[8];
        #pragma unroll
        for (int j = 0; j < 4; ++j) unpack2(acc[i][j], v[2 * j], v[2 * j + 1]);
        #pragma unroll
        for (int j = 0; j < 8; ++j) {
            v[j] += bb[j];
            if (RELU) v[j] = fmaxf(v[j], 0.0f);
        }
        float* cp = C + (long)(crow + i) * N + ccol;
        *(float4*)&cp[0] = *(float4*)&v[0];
        *(float4*)&cp[4] = *(float4*)&v[4];
    }
}

// ---------------------------------------------------------------------------
// MLP layer 2 + softmax
// ---------------------------------------------------------------------------
__global__ __launch_bounds__(256)
void mlp2_softmax_kernel(const float* __restrict__ enc,
                         const float* __restrict__ w2,
                         const float* __restrict__ b2,
                         float* __restrict__ out)
{
    __shared__ float w2s[NCLS * MLPH];
    __shared__ float b2s[NCLS];
    const int tid = threadIdx.y * 16 + threadIdx.x;
    for (int i = tid; i < NCLS * MLPH; i += 256) w2s[i] = w2[i];
    if (tid < NCLS) b2s[tid] = b2[tid];
    __syncthreads();

    const int row = blockIdx.x * 16 + threadIdx.y;
    const int c   = threadIdx.x;

    const float4* e4 = (const float4*)(enc + (long)row * MLPH);
    const float4* w4 = (const float4*)(w2s + c * MLPH);
    float acc = 0.0f;
    #pragma unroll
    for (int k = 0; k < MLPH / 4; ++k) {
        float4 e = e4[k];
        float4 w = w4[k];
        acc += e.x * w.x + e.y * w.y + e.z * w.z + e.w * w.w;
    }
    acc += b2s[c];

    float m = acc;
    #pragma unroll
    for (int d = 8; d >= 1; d >>= 1)
        m = fmaxf(m, __shfl_xor_sync(0xffffffffu, m, d, 16));
    float e = expf(acc - m);
    float s = e;
    #pragma unroll
    for (int d = 8; d >= 1; d >>= 1)
        s += __shfl_xor_sync(0xffffffffu, s, d, 16);
    out[(long)row * NCLS + c] = e / s;
}

// ---------------------------------------------------------------------------
extern "C" void kernel_launch(void* const* d_in, const int* in_sizes, int n_in,
                              void* d_out, int out_size)
{
    const float* A   = (const float*)d_in[0];
    const float* x0  = (const float*)d_in[1];
    const float* gw  = (const float*)d_in[2];
    const float* gb  = (const float*)d_in[3];
    const float* w1  = (const float*)d_in[4];
    const float* b1  = (const float*)d_in[5];
    const float* w2  = (const float*)d_in[6];
    const float* b2  = (const float*)d_in[7];
    const int*   idx = (const int*)d_in[8];
    float* out = (float*)d_out;

    static float *gy = nullptr, *gx = nullptr;
    static __nv_bfloat16 *ah = nullptr, *al = nullptr, *xh = nullptr, *xl = nullptr;
    if (!gy) {
        cudaGetSymbolAddress((void**)&gy, g_y);
        cudaGetSymbolAddress((void**)&gx, g_x);
        cudaGetSymbolAddress((void**)&ah, g_Ah);
        cudaGetSymbolAddress((void**)&al, g_Al);
        cudaGetSymbolAddress((void**)&xh, g_Xh);
        cudaGetSymbolAddress((void**)&xl, g_Xl);
        cudaFuncSetAttribute(gcn_ax_bf16_kernel,
                             cudaFuncAttributeMaxDynamicSharedMemorySize,
                             2 * STAGE_B);
    }

    // split A (runs every replay; A is an input)
    {
        long n8 = (long)N_NODES * N_NODES / 8;
        split_a_kernel<<<(unsigned)(n8 / 256), 256>>>(A, ah, al);
    }

    const dim3 blk(256);
    const dim3 gridBig(F_DIM / 128, N_NODES / 128);   // (2,128)
    const dim3 gridEnc(MLPH / 128, NIDX / 128);       // (1,64)
    const dim3 gridXT(F_DIM / 32, N_NODES / 32);      // (8,512)

    const float* xin = x0;
    for (int l = 0; l < 3; ++l) {
        split_xt_kernel<<<gridXT, dim3(32, 8)>>>(xin, xh, xl);
        gcn_ax_bf16_kernel<<<gridBig, blk, 2 * STAGE_B>>>(ah, al, xh, xl, gy);
        sgemm_bt_kernel<true, false><<<gridBig, blk>>>(
            gy, gw + (long)l * F_DIM * F_DIM, gb + (long)l * F_DIM, nullptr,
            gx, N_NODES, F_DIM, F_DIM);
        xin = gx;
    }

    sgemm_bt_kernel<true, true><<<gridEnc, blk>>>(
        gx, w1, b1, idx, out, NIDX, MLPH, F_DIM);

    mlp2_softmax_kernel<<<NIDX / 16, dim3(16, 16)>>>(
        out, w2, b2, out + (long)NIDX * MLPH);
}